// round 6
// baseline (speedup 1.0000x reference)
#include <cuda_runtime.h>
#include <math.h>

#define LD2   68          // row stride in float2 units; LD2 % 16 == 4 -> conflict-free 64b frags
#define EPSV  1e-4f
#define NAGG  5
#define NITER 10          // 5 aggressive + 5 Newton-Schulz polish

// round-to-nearest fp32 -> tf32 (valid fp32 bit pattern, low 13 mantissa bits zero)
__device__ __forceinline__ unsigned f2tf(float x) {
    unsigned r; asm("cvt.rna.tf32.f32 %0, %1;" : "=r"(r) : "f"(x)); return r;
}

// split v into {hi, lo}, both tf32-valued; hi + lo == v to ~2^-24 relative
__device__ __forceinline__ float2 split2(float v) {
    float hf = __uint_as_float(f2tf(v));
    float lf = __uint_as_float(f2tf(v - hf));
    return make_float2(hf, lf);
}

__device__ __forceinline__ void mma8(float* d, const unsigned* a, const unsigned* b) {
    asm volatile("mma.sync.aligned.m16n8k8.row.col.f32.tf32.tf32.f32 "
                 "{%0,%1,%2,%3}, {%4,%5,%6,%7}, {%8,%9}, {%0,%1,%2,%3};"
                 : "+f"(d[0]), "+f"(d[1]), "+f"(d[2]), "+f"(d[3])
                 : "r"(a[0]), "r"(a[1]), "r"(a[2]), "r"(a[3]), "r"(b[0]), "r"(b[1]));
}

// Warp computes a 16x32 tile of D = A * B from PRE-SPLIT smem (no cvt in loop).
// NS=3 -> hi*hi + lo*hi + hi*lo (fp32-class); NS=1 -> hi*hi only (scale prep).
template<int NS>
__device__ __forceinline__ void warp_gemm(float acc[4][4],
                                          const float2* __restrict__ As,
                                          const float2* __restrict__ Bs,
                                          int mr, int nc, int g, int t4)
{
#pragma unroll
    for (int nt = 0; nt < 4; nt++)
#pragma unroll
        for (int i = 0; i < 4; i++) acc[nt][i] = 0.0f;

#pragma unroll
    for (int k0 = 0; k0 < 64; k0 += 8) {
        // B fragments: B[k0+t4][nc+8nt+g] and +4 k-rows
        unsigned bhi[4][2], blo[4][2];
        const float2* bp = Bs + (k0 + t4) * LD2 + nc + g;
#pragma unroll
        for (int nt = 0; nt < 4; nt++) {
            float2 y0 = bp[nt * 8];
            float2 y1 = bp[4 * LD2 + nt * 8];
            bhi[nt][0] = __float_as_uint(y0.x); bhi[nt][1] = __float_as_uint(y1.x);
            if (NS == 3) {
                blo[nt][0] = __float_as_uint(y0.y); blo[nt][1] = __float_as_uint(y1.y);
            }
        }
        // A fragment: rows mr+g / mr+8+g, cols k0+t4 / k0+t4+4
        unsigned ahi[4], alo[4];
        const float2* ap = As + (mr + g) * LD2 + k0 + t4;
        float2 a0 = ap[0];
        float2 a1 = ap[8 * LD2];
        float2 a2 = ap[4];
        float2 a3 = ap[8 * LD2 + 4];
        ahi[0] = __float_as_uint(a0.x); ahi[1] = __float_as_uint(a1.x);
        ahi[2] = __float_as_uint(a2.x); ahi[3] = __float_as_uint(a3.x);
        if (NS == 3) {
            alo[0] = __float_as_uint(a0.y); alo[1] = __float_as_uint(a1.y);
            alo[2] = __float_as_uint(a2.y); alo[3] = __float_as_uint(a3.y);
        }
#pragma unroll
        for (int nt = 0; nt < 4; nt++) {
            mma8(acc[nt], ahi, bhi[nt]);
            if (NS == 3) {
                mma8(acc[nt], alo, bhi[nt]);
                mma8(acc[nt], ahi, blo[nt]);
            }
        }
    }
}

// store 16x32 tile into split smem: one STS.128 per element pair
__device__ __forceinline__ void store_acc_split(float2* __restrict__ D,
                                                const float acc[4][4],
                                                int mr, int nc, int g, int t4)
{
#pragma unroll
    for (int nt = 0; nt < 4; nt++) {
        int r = mr + g, c = nc + nt * 8 + 2 * t4;
        float2 p0 = split2(acc[nt][0]);
        float2 p1 = split2(acc[nt][1]);
        *(float4*)&D[r * LD2 + c] = make_float4(p0.x, p0.y, p1.x, p1.y);
        float2 p2 = split2(acc[nt][2]);
        float2 p3 = split2(acc[nt][3]);
        *(float4*)&D[(r + 8) * LD2 + c] = make_float4(p2.x, p2.y, p3.x, p3.y);
    }
}

extern "C" __global__ void __launch_bounds__(256, 3)
reeig6(const float* __restrict__ xg, float* __restrict__ outg, int nmat)
{
    extern __shared__ float2 sm2[];
    float2* S2  = sm2;                   // split sign iterate
    float2* P2  = S2 + 64 * LD2;         // split scratch (S^2 / A)
    float*  red = (float*)(P2 + 64 * LD2);

    const int mat = blockIdx.x;
    if (mat >= nmat) return;
    const float* X = xg + (size_t)mat * 4096;
    float*       O = outg + (size_t)mat * 4096;

    const int t = threadIdx.x;
    const int warp = t >> 5, lane = t & 31;
    const int g = lane >> 2, t4 = lane & 3;
    const int mr = (warp & 3) * 16;      // 8 warps: 4 row-bands x 2 col-bands
    const int nc = (warp >> 2) * 32;

    // S <- split(A = X - eps*I)
    for (int idx = t; idx < 4096; idx += 256) {
        int r = idx >> 6, c = idx & 63;
        float v = X[idx];
        if (r == c) v -= EPSV;
        S2[r * LD2 + c] = split2(v);
    }
    __syncthreads();

    float acc[4][4];

    // ---- scale estimate (hi-only TF32: feeds s, 2% margin absorbs error) ----
    warp_gemm<1>(acc, S2, S2, mr, nc, g, t4);      // P = A^2
    store_acc_split(P2, acc, mr, nc, g, t4);
    __syncthreads();
    warp_gemm<1>(acc, P2, P2, mr, nc, g, t4);      // acc = A^4 (no store)
    float part = 0.0f;
#pragma unroll
    for (int nt = 0; nt < 4; nt++)
#pragma unroll
        for (int i = 0; i < 4; i++) part = fmaf(acc[nt][i], acc[nt][i], part);
#pragma unroll
    for (int off = 16; off; off >>= 1)
        part += __shfl_xor_sync(0xffffffffu, part, off);
    if (lane == 0) red[warp] = part;
    __syncthreads();
    if (t == 0) {
        float tot = 0.0f;
        for (int w = 0; w < 8; w++) tot += red[w];
        // s = 1.02 * ||A^4||_F^(1/4) = 1.02 * tot^(1/8) >= 1.02 * lambda_max
        float s = 1.02f * exp2f(0.125f * log2f(fmaxf(tot, 1e-30f)));
        red[8] = 1.0f / s;
    }
    __syncthreads();
    const float inv_s = red[8];

    // S <- split(A / s)   (spectrum in [-0.98, 0.98])
    for (int idx = t; idx < 4096; idx += 256) {
        int r = idx >> 6, c = idx & 63;
        float2 e = S2[r * LD2 + c];
        S2[r * LD2 + c] = split2((e.x + e.y) * inv_s);
    }
    __syncthreads();

    // ---- sign iterations: S <- ca*S + cb*S^3, in place ----
#pragma unroll 1
    for (int it = 0; it < NITER; it++) {
        const float ca = (it < NAGG) ? 2.325f      : 1.5f;
        const float cb = (it < NAGG) ? -1.8619375f : -0.5f;

        warp_gemm<3>(acc, S2, S2, mr, nc, g, t4);  // P = S^2
        store_acc_split(P2, acc, mr, nc, g, t4);
        __syncthreads();

        warp_gemm<3>(acc, S2, P2, mr, nc, g, t4);  // acc = S^3
        // fold ca*S into acc (S reads complete before barrier below)
#pragma unroll
        for (int nt = 0; nt < 4; nt++) {
            int r = mr + g, c = nc + nt * 8 + 2 * t4;
            float4 s1 = *(const float4*)&S2[r * LD2 + c];
            float4 s2 = *(const float4*)&S2[(r + 8) * LD2 + c];
            acc[nt][0] = fmaf(cb, acc[nt][0], ca * (s1.x + s1.y));
            acc[nt][1] = fmaf(cb, acc[nt][1], ca * (s1.z + s1.w));
            acc[nt][2] = fmaf(cb, acc[nt][2], ca * (s2.x + s2.y));
            acc[nt][3] = fmaf(cb, acc[nt][3], ca * (s2.z + s2.w));
        }
        __syncthreads();                           // all S reads done
        store_acc_split(S2, acc, mr, nc, g, t4);   // in-place update
        __syncthreads();
    }

    // ---- final: reload A into P, M = S*A ~= |A| ----
    for (int idx = t; idx < 4096; idx += 256) {
        int r = idx >> 6, c = idx & 63;
        float v = X[idx];
        if (r == c) v -= EPSV;
        P2[r * LD2 + c] = split2(v);
    }
    __syncthreads();

    warp_gemm<3>(acc, S2, P2, mr, nc, g, t4);      // acc = M = S*A
    __syncthreads();                               // all S reads done
    store_acc_split(S2, acc, mr, nc, g, t4);       // S <- M
    __syncthreads();

    // out = A/2 + eps*I + (M + M^T)/4
    for (int idx = t; idx < 4096; idx += 256) {
        int r = idx >> 6, c = idx & 63;
        float2 ae = P2[r * LD2 + c];
        float2 m1 = S2[r * LD2 + c];
        float2 m2 = S2[c * LD2 + r];
        float v = 0.5f * (ae.x + ae.y)
                + 0.25f * ((m1.x + m1.y) + (m2.x + m2.y));
        if (r == c) v += EPSV;
        O[idx] = v;
    }
}

extern "C" void kernel_launch(void* const* d_in, const int* in_sizes, int n_in,
                              void* d_out, int out_size)
{
    const float* x  = (const float*)d_in[0];
    float* out      = (float*)d_out;
    const int nmat  = in_sizes[0] / 4096;

    const int smem_bytes = 2 * 64 * LD2 * (int)sizeof(float2) + 64;   // 69696
    cudaFuncSetAttribute(reeig6, cudaFuncAttributeMaxDynamicSharedMemorySize,
                         smem_bytes);
    reeig6<<<nmat, 256, smem_bytes>>>(x, out, nmat);
}

// round 7
// speedup vs baseline: 1.0008x; 1.0008x over previous
#include <cuda_runtime.h>
#include <math.h>

#define LD2   68          // row stride in float2 units; LD2 % 16 == 4 -> conflict-free 64b frags
#define EPSV  1e-4f
#define NAGG  5
#define NITER 10          // 5 aggressive + 5 Newton-Schulz polish

// round-to-nearest fp32 -> tf32 (valid fp32 bit pattern, low 13 mantissa bits zero)
__device__ __forceinline__ unsigned f2tf(float x) {
    unsigned r; asm("cvt.rna.tf32.f32 %0, %1;" : "=r"(r) : "f"(x)); return r;
}

// split v into {hi, lo}, both tf32-valued; hi + lo == v to ~2^-24 relative
__device__ __forceinline__ float2 split2(float v) {
    float hf = __uint_as_float(f2tf(v));
    float lf = __uint_as_float(f2tf(v - hf));
    return make_float2(hf, lf);
}

__device__ __forceinline__ void mma8(float* d, const unsigned* a, const unsigned* b) {
    asm volatile("mma.sync.aligned.m16n8k8.row.col.f32.tf32.tf32.f32 "
                 "{%0,%1,%2,%3}, {%4,%5,%6,%7}, {%8,%9}, {%0,%1,%2,%3};"
                 : "+f"(d[0]), "+f"(d[1]), "+f"(d[2]), "+f"(d[3])
                 : "r"(a[0]), "r"(a[1]), "r"(a[2]), "r"(a[3]), "r"(b[0]), "r"(b[1]));
}

// Warp computes a 16x32 tile of D = A * B from PRE-SPLIT smem (no cvt in loop).
// NS=3 -> hi*hi + lo*hi + hi*lo (fp32-class); NS=1 -> hi*hi only (scale prep).
template<int NS>
__device__ __forceinline__ void warp_gemm(float acc[4][4],
                                          const float2* __restrict__ As,
                                          const float2* __restrict__ Bs,
                                          int mr, int nc, int g, int t4)
{
#pragma unroll
    for (int nt = 0; nt < 4; nt++)
#pragma unroll
        for (int i = 0; i < 4; i++) acc[nt][i] = 0.0f;

#pragma unroll
    for (int k0 = 0; k0 < 64; k0 += 8) {
        // B fragments: B[k0+t4][nc+8nt+g] and +4 k-rows
        unsigned bhi[4][2], blo[4][2];
        const float2* bp = Bs + (k0 + t4) * LD2 + nc + g;
#pragma unroll
        for (int nt = 0; nt < 4; nt++) {
            float2 y0 = bp[nt * 8];
            float2 y1 = bp[4 * LD2 + nt * 8];
            bhi[nt][0] = __float_as_uint(y0.x); bhi[nt][1] = __float_as_uint(y1.x);
            if (NS == 3) {
                blo[nt][0] = __float_as_uint(y0.y); blo[nt][1] = __float_as_uint(y1.y);
            }
        }
        // A fragment: rows mr+g / mr+8+g, cols k0+t4 / k0+t4+4
        unsigned ahi[4], alo[4];
        const float2* ap = As + (mr + g) * LD2 + k0 + t4;
        float2 a0 = ap[0];
        float2 a1 = ap[8 * LD2];
        float2 a2 = ap[4];
        float2 a3 = ap[8 * LD2 + 4];
        ahi[0] = __float_as_uint(a0.x); ahi[1] = __float_as_uint(a1.x);
        ahi[2] = __float_as_uint(a2.x); ahi[3] = __float_as_uint(a3.x);
        if (NS == 3) {
            alo[0] = __float_as_uint(a0.y); alo[1] = __float_as_uint(a1.y);
            alo[2] = __float_as_uint(a2.y); alo[3] = __float_as_uint(a3.y);
        }
#pragma unroll
        for (int nt = 0; nt < 4; nt++) {
            mma8(acc[nt], ahi, bhi[nt]);
            if (NS == 3) {
                mma8(acc[nt], alo, bhi[nt]);
                mma8(acc[nt], ahi, blo[nt]);
            }
        }
    }
}

// store 16x32 tile into split smem: one STS.128 per element pair
__device__ __forceinline__ void store_acc_split(float2* __restrict__ D,
                                                const float acc[4][4],
                                                int mr, int nc, int g, int t4)
{
#pragma unroll
    for (int nt = 0; nt < 4; nt++) {
        int r = mr + g, c = nc + nt * 8 + 2 * t4;
        float2 p0 = split2(acc[nt][0]);
        float2 p1 = split2(acc[nt][1]);
        *(float4*)&D[r * LD2 + c] = make_float4(p0.x, p0.y, p1.x, p1.y);
        float2 p2 = split2(acc[nt][2]);
        float2 p3 = split2(acc[nt][3]);
        *(float4*)&D[(r + 8) * LD2 + c] = make_float4(p2.x, p2.y, p3.x, p3.y);
    }
}

extern "C" __global__ void __launch_bounds__(256, 3)
reeig6(const float* __restrict__ xg, float* __restrict__ outg, int nmat)
{
    extern __shared__ float2 sm2[];
    float2* S2  = sm2;                   // split sign iterate
    float2* P2  = S2 + 64 * LD2;         // split scratch (S^2 / A)
    float*  red = (float*)(P2 + 64 * LD2);

    const int mat = blockIdx.x;
    if (mat >= nmat) return;
    const float* X = xg + (size_t)mat * 4096;
    float*       O = outg + (size_t)mat * 4096;

    const int t = threadIdx.x;
    const int warp = t >> 5, lane = t & 31;
    const int g = lane >> 2, t4 = lane & 3;
    const int mr = (warp & 3) * 16;      // 8 warps: 4 row-bands x 2 col-bands
    const int nc = (warp >> 2) * 32;

    // S <- split(A = X - eps*I)
    for (int idx = t; idx < 4096; idx += 256) {
        int r = idx >> 6, c = idx & 63;
        float v = X[idx];
        if (r == c) v -= EPSV;
        S2[r * LD2 + c] = split2(v);
    }
    __syncthreads();

    float acc[4][4];

    // ---- scale estimate (hi-only TF32: feeds s, 2% margin absorbs error) ----
    warp_gemm<1>(acc, S2, S2, mr, nc, g, t4);      // P = A^2
    store_acc_split(P2, acc, mr, nc, g, t4);
    __syncthreads();
    warp_gemm<1>(acc, P2, P2, mr, nc, g, t4);      // acc = A^4 (no store)
    float part = 0.0f;
#pragma unroll
    for (int nt = 0; nt < 4; nt++)
#pragma unroll
        for (int i = 0; i < 4; i++) part = fmaf(acc[nt][i], acc[nt][i], part);
#pragma unroll
    for (int off = 16; off; off >>= 1)
        part += __shfl_xor_sync(0xffffffffu, part, off);
    if (lane == 0) red[warp] = part;
    __syncthreads();
    if (t == 0) {
        float tot = 0.0f;
        for (int w = 0; w < 8; w++) tot += red[w];
        // s = 1.02 * ||A^4||_F^(1/4) = 1.02 * tot^(1/8) >= 1.02 * lambda_max
        float s = 1.02f * exp2f(0.125f * log2f(fmaxf(tot, 1e-30f)));
        red[8] = 1.0f / s;
    }
    __syncthreads();
    const float inv_s = red[8];

    // S <- split(A / s)   (spectrum in [-0.98, 0.98])
    for (int idx = t; idx < 4096; idx += 256) {
        int r = idx >> 6, c = idx & 63;
        float2 e = S2[r * LD2 + c];
        S2[r * LD2 + c] = split2((e.x + e.y) * inv_s);
    }
    __syncthreads();

    // ---- sign iterations: S <- ca*S + cb*S^3, in place ----
#pragma unroll 1
    for (int it = 0; it < NITER; it++) {
        const float ca = (it < NAGG) ? 2.325f      : 1.5f;
        const float cb = (it < NAGG) ? -1.8619375f : -0.5f;

        warp_gemm<3>(acc, S2, S2, mr, nc, g, t4);  // P = S^2
        store_acc_split(P2, acc, mr, nc, g, t4);
        __syncthreads();

        warp_gemm<3>(acc, S2, P2, mr, nc, g, t4);  // acc = S^3
        // fold ca*S into acc (S reads complete before barrier below)
#pragma unroll
        for (int nt = 0; nt < 4; nt++) {
            int r = mr + g, c = nc + nt * 8 + 2 * t4;
            float4 s1 = *(const float4*)&S2[r * LD2 + c];
            float4 s2 = *(const float4*)&S2[(r + 8) * LD2 + c];
            acc[nt][0] = fmaf(cb, acc[nt][0], ca * (s1.x + s1.y));
            acc[nt][1] = fmaf(cb, acc[nt][1], ca * (s1.z + s1.w));
            acc[nt][2] = fmaf(cb, acc[nt][2], ca * (s2.x + s2.y));
            acc[nt][3] = fmaf(cb, acc[nt][3], ca * (s2.z + s2.w));
        }
        __syncthreads();                           // all S reads done
        store_acc_split(S2, acc, mr, nc, g, t4);   // in-place update
        __syncthreads();
    }

    // ---- final: reload A into P, M = S*A ~= |A| ----
    for (int idx = t; idx < 4096; idx += 256) {
        int r = idx >> 6, c = idx & 63;
        float v = X[idx];
        if (r == c) v -= EPSV;
        P2[r * LD2 + c] = split2(v);
    }
    __syncthreads();

    warp_gemm<3>(acc, S2, P2, mr, nc, g, t4);      // acc = M = S*A
    __syncthreads();                               // all S reads done
    store_acc_split(S2, acc, mr, nc, g, t4);       // S <- M
    __syncthreads();

    // out = A/2 + eps*I + (M + M^T)/4
    for (int idx = t; idx < 4096; idx += 256) {
        int r = idx >> 6, c = idx & 63;
        float2 ae = P2[r * LD2 + c];
        float2 m1 = S2[r * LD2 + c];
        float2 m2 = S2[c * LD2 + r];
        float v = 0.5f * (ae.x + ae.y)
                + 0.25f * ((m1.x + m1.y) + (m2.x + m2.y));
        if (r == c) v += EPSV;
        O[idx] = v;
    }
}

extern "C" void kernel_launch(void* const* d_in, const int* in_sizes, int n_in,
                              void* d_out, int out_size)
{
    const float* x  = (const float*)d_in[0];
    float* out      = (float*)d_out;
    const int nmat  = in_sizes[0] / 4096;

    const int smem_bytes = 2 * 64 * LD2 * (int)sizeof(float2) + 64;   // 69696
    cudaFuncSetAttribute(reeig6, cudaFuncAttributeMaxDynamicSharedMemorySize,
                         smem_bytes);
    reeig6<<<nmat, 256, smem_bytes>>>(x, out, nmat);
}